// round 4
// baseline (speedup 1.0000x reference)
#include <cuda_runtime.h>
#include <cuda_bf16.h>
#include <math.h>
#include <cstdint>

#define NROWS 8192
#define DDIM  64
#define MARGIN 1.1f
#define EPS 1e-8f
#define TILE 128
#define NTILES (NROWS / TILE)            // 64
#define NBLOCKS (NTILES * (NTILES + 1) / 2)  // 2080 upper-tri tiles
#define ROWB  144                        // padded smem row stride (bytes)

// Scratch (no allocs allowed).
__device__ __align__(16) __nv_bfloat16 g_xb[NROWS * DDIM];
__device__ double   g_accum;      // zero-init; last block resets each launch
__device__ unsigned g_prep_done;  // idem
__device__ unsigned g_done_ctr;   // idem

__device__ __forceinline__ uint32_t smem_u32(const void* p) {
    uint32_t a;
    asm("{ .reg .u64 t; cvta.to.shared.u64 t, %1; cvt.u32.u64 %0, t; }"
        : "=r"(a) : "l"(p));
    return a;
}

__device__ __forceinline__ void ldsm_x4(uint32_t& r0, uint32_t& r1,
                                        uint32_t& r2, uint32_t& r3,
                                        uint32_t addr) {
    asm volatile("ldmatrix.sync.aligned.m8n8.x4.shared.b16 {%0,%1,%2,%3}, [%4];"
                 : "=r"(r0), "=r"(r1), "=r"(r2), "=r"(r3) : "r"(addr));
}

__device__ __forceinline__ void mma_16816(float* c, const uint32_t* a,
                                          uint32_t b0, uint32_t b1) {
    asm volatile(
        "mma.sync.aligned.m16n8k16.row.col.f32.bf16.bf16.f32 "
        "{%0,%1,%2,%3}, {%4,%5,%6,%7}, {%8,%9}, {%0,%1,%2,%3};"
        : "+f"(c[0]), "+f"(c[1]), "+f"(c[2]), "+f"(c[3])
        : "r"(a[0]), "r"(a[1]), "r"(a[2]), "r"(a[3]), "r"(b0), "r"(b1));
}

// ---------------------------------------------------------------------------
// Single fused kernel: prep (blocks 0..63) -> device barrier on prep
// -> triangular Gram tile + hinge epilogue -> atomic reduce -> last block
// finalizes output and resets state.
// ---------------------------------------------------------------------------
__global__ __launch_bounds__(256, 2) void fused_kernel(
    const float* __restrict__ x, const int* __restrict__ cls,
    float* __restrict__ out) {

    const int bid  = blockIdx.x;
    const int tid  = threadIdx.x;
    const int wid  = tid >> 5;
    const int lane = tid & 31;

    // ---------------- Phase 1: prep (normalize -> bf16), blocks 0..63 ------
    if (bid < NROWS / TILE) {
        // 2 threads per row: thread handles 32 floats (8 float4), MLP-batched.
        int t    = bid * 256 + tid;       // [0, 16384)
        int row  = t >> 1;
        int half = t & 1;
        const float4* xr = (const float4*)(x + (size_t)row * DDIM + half * 32);
        float4 v[8];
        #pragma unroll
        for (int i = 0; i < 8; i++) v[i] = xr[i];
        float s = 0.0f;
        #pragma unroll
        for (int i = 0; i < 8; i++)
            s += v[i].x * v[i].x + v[i].y * v[i].y +
                 v[i].z * v[i].z + v[i].w * v[i].w;
        s += __shfl_xor_sync(0xffffffffu, s, 1);   // partner has other half
        float inv = 1.0f / fmaxf(sqrtf(s), EPS);

        __nv_bfloat16* dst = g_xb + (size_t)row * DDIM + half * 32;
        #pragma unroll
        for (int i = 0; i < 8; i++) {
            __nv_bfloat162 p0 = {__float2bfloat16(v[i].x * inv),
                                 __float2bfloat16(v[i].y * inv)};
            __nv_bfloat162 p1 = {__float2bfloat16(v[i].z * inv),
                                 __float2bfloat16(v[i].w * inv)};
            *(__nv_bfloat162*)(dst + i * 4)     = p0;
            *(__nv_bfloat162*)(dst + i * 4 + 2) = p1;
        }
        __syncthreads();
        if (tid == 0) {
            __threadfence();                      // publish g_xb
            atomicAdd(&g_prep_done, 1u);
        }
    }

    // ---------------- Device-wide wait for prep ----------------------------
    if (tid == 0) {
        unsigned v;
        do {
            asm volatile("ld.acquire.gpu.u32 %0, [%1];"
                         : "=r"(v) : "l"(&g_prep_done));
            if (v < (unsigned)(NROWS / TILE)) __nanosleep(64);
        } while (v < (unsigned)(NROWS / TILE));
    }
    __syncthreads();

    // ---------------- Phase 2: triangular tile (bi <= bj) ------------------
    int bi = (int)((129.0f - sqrtf(16641.0f - 8.0f * (float)bid)) * 0.5f);
    while (bi * (129 - bi) / 2 > bid) bi--;
    while ((bi + 1) * (128 - bi) / 2 <= bid) bi++;
    const int bj = bi + (bid - bi * (129 - bi) / 2);
    const bool diag = (bi == bj);

    __shared__ __align__(16) char As[TILE * ROWB];
    __shared__ __align__(16) char Bs_[TILE * ROWB];
    __shared__ int   csi[TILE];
    __shared__ int   csj[TILE];
    __shared__ float red[8];

    const uint4* Ag = (const uint4*)(g_xb + (size_t)bi * TILE * DDIM);
    #pragma unroll
    for (int r = 0; r < 4; r++) {
        int idx = tid + r * 256;        // [0,1024)
        int row = idx >> 3;
        int ch  = idx & 7;
        *(uint4*)(As + row * ROWB + ch * 16) = Ag[idx];
    }
    if (!diag) {
        const uint4* Bg = (const uint4*)(g_xb + (size_t)bj * TILE * DDIM);
        #pragma unroll
        for (int r = 0; r < 4; r++) {
            int idx = tid + r * 256;
            int row = idx >> 3;
            int ch  = idx & 7;
            *(uint4*)(Bs_ + row * ROWB + ch * 16) = Bg[idx];
        }
    }
    if (tid < TILE) csi[tid]        = cls[bi * TILE + tid];
    else            csj[tid - TILE] = cls[bj * TILE + (tid - TILE)];
    __syncthreads();

    const uint32_t a_base = smem_u32(As);
    const uint32_t b_base = diag ? a_base : smem_u32(Bs_);
    const int* cj_src = diag ? csi : csj;

    const int wm = wid & 3;
    const int wn = wid >> 2;
    const uint32_t a_lane_off =
        (uint32_t)((wm * 32 + (lane & 15)) * ROWB + ((lane >> 4) << 4));
    const uint32_t b_lane_off =
        (uint32_t)((wn * 64 + (lane & 7) + ((lane >> 4) << 3)) * ROWB +
                   (((lane >> 3) & 1) << 4));

    float c[2][8][4];
    #pragma unroll
    for (int m = 0; m < 2; m++)
        #pragma unroll
        for (int n = 0; n < 8; n++)
            #pragma unroll
            for (int e = 0; e < 4; e++) c[m][n][e] = 0.0f;

    #pragma unroll
    for (int k = 0; k < 4; k++) {          // 4 k-steps of 16 bf16 (32B)
        uint32_t a[2][4];
        #pragma unroll
        for (int m = 0; m < 2; m++)
            ldsm_x4(a[m][0], a[m][1], a[m][2], a[m][3],
                    a_base + a_lane_off + m * 16 * ROWB + k * 32);

        uint32_t b[8][2];
        #pragma unroll
        for (int q = 0; q < 4; q++) {
            uint32_t r0, r1, r2, r3;
            ldsm_x4(r0, r1, r2, r3,
                    b_base + b_lane_off + q * 16 * ROWB + k * 32);
            b[q * 2 + 0][0] = r0; b[q * 2 + 0][1] = r1;
            b[q * 2 + 1][0] = r2; b[q * 2 + 1][1] = r3;
        }

        #pragma unroll
        for (int m = 0; m < 2; m++)
            #pragma unroll
            for (int n = 0; n < 8; n++)
                mma_16816(c[m][n], a[m], b[n][0], b[n][1]);
    }

    // ---------------- Hinge epilogue on fragments ---------------------------
    // loss = same ? (1-c) : max(c + (MARGIN-1), 0)
    const float MC = MARGIN - 1.0f;
    const int quad = lane >> 2;
    const int tq   = lane & 3;
    float lsum = 0.0f;
    #pragma unroll
    for (int m = 0; m < 2; m++) {
        const int ci0 = csi[wm * 32 + m * 16 + quad];
        const int ci1 = csi[wm * 32 + m * 16 + quad + 8];
        #pragma unroll
        for (int n = 0; n < 8; n++) {
            const int colb = wn * 64 + n * 8 + tq * 2;
            const int cj0  = cj_src[colb];
            const int cj1  = cj_src[colb + 1];
            float v0 = c[m][n][0], v1 = c[m][n][1];
            float v2 = c[m][n][2], v3 = c[m][n][3];
            lsum += (ci0 == cj0) ? (1.0f - v0) : fmaxf(v0 + MC, 0.0f);
            lsum += (ci0 == cj1) ? (1.0f - v1) : fmaxf(v1 + MC, 0.0f);
            lsum += (ci1 == cj0) ? (1.0f - v2) : fmaxf(v2 + MC, 0.0f);
            lsum += (ci1 == cj1) ? (1.0f - v3) : fmaxf(v3 + MC, 0.0f);
        }
    }
    if (!diag) lsum *= 2.0f;     // symmetric tile counted once

    // ---------------- Block reduce + global accumulate ----------------------
    #pragma unroll
    for (int o = 16; o; o >>= 1) lsum += __shfl_xor_sync(0xffffffffu, lsum, o);
    if (lane == 0) red[wid] = lsum;
    __syncthreads();
    if (tid == 0) {
        float t = 0.0f;
        #pragma unroll
        for (int w = 0; w < 8; w++) t += red[w];
        atomicAdd(&g_accum, (double)t);
        __threadfence();
        unsigned old = atomicAdd(&g_done_ctr, 1u);
        if (old == (unsigned)(NBLOCKS - 1)) {
            // Every block's accumulation happened-before this point.
            double a = atomicAdd(&g_accum, 0.0);
            out[0] = (float)(a / ((double)NROWS * (double)NROWS));
            // Reset state for the next graph replay.
            g_accum     = 0.0;
            g_done_ctr  = 0u;
            g_prep_done = 0u;
        }
    }
}

extern "C" void kernel_launch(void* const* d_in, const int* in_sizes, int n_in,
                              void* d_out, int out_size) {
    const float* bottleneck = (const float*)d_in[0];
    const int*   class_map  = (const int*)d_in[1];
    float*       out        = (float*)d_out;
    fused_kernel<<<NBLOCKS, 256>>>(bottleneck, class_map, out);
}